// round 13
// baseline (speedup 1.0000x reference)
#include <cuda_runtime.h>
#include <cuda_fp16.h>
#include <cstdint>

// ---------------------------------------------------------------------------
// GatingNetwork: logits = x @ W^T + b ; softmax ; top-2 (values, indices)
// Single-product fp16 HMMA (m16n8k16.f16, fp32 accum). W pre-scaled x256
// (exact), logit = D/256 + b. Logit error sigma ~1.4e-4; tokens with any
// top-3 gap < 8e-4 recomputed exactly in fp32 by the fixup kernel.
// 512 threads, expert-split warps: warp (tg, eh) owns 16 tokens x 32 experts
// -> 4 warps/SMSP for latency hiding with per-SM LDS unchanged.
// Main loop = k256 chunks, 4 k64 halves unrolled inside.
// ---------------------------------------------------------------------------

#define HIDDEN   4096
#define NEXP     64
#define NTOK     16384
#define MTILE    128
#define NCTA     (NTOK / MTILE)        // 128
#define THREADS  512
#define NSTEP    (HIDDEN / 16)         // 256 k16-steps
#define NHALF    (NSTEP / 4)           // 64 k64-halves
#define STEPS_PER_CHUNK 16             // K=256 per W chunk
#define HALVES_PER_CHUNK 4
#define NCHUNK   (NSTEP / STEPS_PER_CHUNK)  // 16
#define GAP_THR  8e-4f
#define WSCALE   256.0f
#define INV_WS   (1.0f / 256.0f)

// per k16 step: 4 mblocks x 32 lanes x uint4 (fp16, single image)
#define FRAG_PER_STEP   (4 * 32)               // 128 uint4 = 2 KB
#define STEP_BYTES      (FRAG_PER_STEP * 16)   // 2048
#define CHUNK_BYTES     (STEPS_PER_CHUNK * STEP_BYTES)  // 32768
#define SMEM_TOTAL      (3 * CHUNK_BYTES)      // 98304

__device__ uint4 g_Wfrag[NSTEP * FRAG_PER_STEP];   // 512 KB
__device__ int   g_flag_count;
__device__ int   g_flag_tokens[NTOK];

static __device__ __forceinline__ uint32_t s2u(const void* p) {
    uint32_t a;
    asm("{ .reg .u64 t; cvta.to.shared.u64 t, %1; cvt.u32.u64 %0, t; }" : "=r"(a) : "l"(p));
    return a;
}

// pack f16x2: hi = f16(f_odd), lo = f16(f_even)
static __device__ __forceinline__ uint32_t pack2h(float f_even, float f_odd) {
    uint32_t r;
    asm("cvt.rn.f16x2.f32 %0, %1, %2;" : "=r"(r) : "f"(f_odd), "f"(f_even));
    return r;
}

#define MMA(D, A, B0, B1)                                                     \
    asm volatile(                                                             \
        "mma.sync.aligned.m16n8k16.row.col.f32.f16.f16.f32 "                  \
        "{%0,%1,%2,%3},{%4,%5,%6,%7},{%8,%9},{%0,%1,%2,%3};"                  \
        : "+f"((D)[0]), "+f"((D)[1]), "+f"((D)[2]), "+f"((D)[3])              \
        : "r"((A)[0]), "r"((A)[1]), "r"((A)[2]), "r"((A)[3]), "r"(B0), "r"(B1))

#define LDS128(R, addr)                                                       \
    asm volatile("ld.shared.v4.b32 {%0,%1,%2,%3}, [%4];"                      \
                 : "=r"((R)[0]), "=r"((R)[1]), "=r"((R)[2]), "=r"((R)[3])     \
                 : "r"(addr))

static __device__ __forceinline__ void cp16(uint32_t sdst, const void* gsrc) {
    asm volatile("cp.async.cg.shared.global [%0], [%1], 16;"
                 :: "r"(sdst), "l"(gsrc) : "memory");
}

// ---------------------------------------------------------------------------
// Prep: W * 256 -> fp16 fragments with the permuted-K layout.
// idx = (t*4 + mb)*32 + lane.
// ---------------------------------------------------------------------------
__global__ void prep_w_kernel(const float* __restrict__ W) {
    int idx = blockIdx.x * blockDim.x + threadIdx.x;
    if (idx == 0) g_flag_count = 0;
    if (idx >= NSTEP * FRAG_PER_STEP) return;
    int l = idx & 31;
    int r = idx >> 5;
    int mb = r & 3;
    int t = r >> 2;

    int q = l & 3;
    int row0 = mb * 16 + (l >> 2);
    int row1 = row0 + 8;
    int c = t * 16 + 4 * q;

    const float* w0 = W + (size_t)row0 * HIDDEN + c;
    const float* w1 = W + (size_t)row1 * HIDDEN + c;

    uint4 v;
    v.x = pack2h(w0[0] * WSCALE, w0[1] * WSCALE);
    v.y = pack2h(w1[0] * WSCALE, w1[1] * WSCALE);
    v.z = pack2h(w0[2] * WSCALE, w0[3] * WSCALE);
    v.w = pack2h(w1[2] * WSCALE, w1[3] * WSCALE);
    g_Wfrag[idx] = v;
}

// ---------------------------------------------------------------------------
// Main kernel: 16 warps; warp (tg = w&7, eh = w>>3) owns tokens
// [blk*128 + tg*16, +16) x experts [eh*32, +32) (mblocks eh*2, eh*2+1).
// One loop iteration = one k256 chunk; per warp per k64 half: 16 HMMA.
// ---------------------------------------------------------------------------
__global__ __launch_bounds__(THREADS, 1)
void gating_kernel(const float* __restrict__ x,
                   const float* __restrict__ bias,
                   float* __restrict__ out) {
    extern __shared__ char smem[];
    const uint32_t sb = s2u(smem);
    const int tid = threadIdx.x;
    const int w   = tid >> 5;
    const int l   = tid & 31;
    const int q   = l & 3;
    const int tg  = w & 7;
    const int eh  = w >> 3;

    auto issue_chunk = [&](int ch) {
        const char* gsrc = (const char*)g_Wfrag + (size_t)ch * CHUNK_BYTES;
        uint32_t sdst = sb + (ch % 3) * CHUNK_BYTES;
#pragma unroll
        for (int i = 0; i < CHUNK_BYTES / 16 / THREADS; i++) {
            int off = (tid + i * THREADS) * 16;
            cp16(sdst + off, gsrc + off);
        }
        asm volatile("cp.async.commit_group;" ::: "memory");
    };

    issue_chunk(0);
    issue_chunk(1);

    // lane's x rows: token tbase + l/4 (g1: +8); within k16-step: float4 at 4q
    const int tbase = blockIdx.x * MTILE + tg * 16;
    const float* p0 = x + (size_t)(tbase + (l >> 2)) * HIDDEN + 4 * q;
    const float* p1 = p0 + (size_t)8 * HIDDEN;

    // x pipeline: [slot][substep][g] float4, slot = k64-half parity
    float4 vx[2][4][2];
#pragma unroll
    for (int d = 0; d < 2; d++)
#pragma unroll
        for (int su = 0; su < 4; su++) {
            vx[d][su][0] = *(const float4*)(p0 + (size_t)(4 * d + su) * 16);
            vx[d][su][1] = *(const float4*)(p1 + (size_t)(4 * d + su) * 16);
        }

    float D[2][2][4];
#pragma unroll
    for (int mb = 0; mb < 2; mb++)
#pragma unroll
        for (int g = 0; g < 2; g++)
#pragma unroll
            for (int i = 0; i < 4; i++) D[mb][g][i] = 0.0f;

#pragma unroll 1
    for (int ch = 0; ch < NCHUNK; ch++) {
        if (ch < NCHUNK - 1)
            asm volatile("cp.async.wait_group 1;" ::: "memory");
        else
            asm volatile("cp.async.wait_group 0;" ::: "memory");
        __syncthreads();
        if (ch + 2 < NCHUNK) issue_chunk(ch + 2);

        const uint32_t cbase = sb + (ch % 3) * CHUNK_BYTES + l * 16;

        // ---- four k64 halves, fully unrolled ----
#pragma unroll
        for (int half = 0; half < HALVES_PER_CHUNK; half++) {
            const int hidx = HALVES_PER_CHUNK * ch + half;  // global k64-half
            const int slot = hidx & 1;

            // B fragments: Bs[substep][g][2] straight from float4
            uint32_t Bs[4][2][2];
#pragma unroll
            for (int su = 0; su < 4; su++)
#pragma unroll
                for (int g = 0; g < 2; g++) {
                    float4 f = vx[slot][su][g];
                    Bs[su][g][0] = pack2h(f.x, f.y);   // slots 2q,2q+1
                    Bs[su][g][1] = pack2h(f.z, f.w);   // slots 2q+8,2q+9
                }

            // prefetch x for half hidx+2 into this slot
            if (hidx + 2 < NHALF) {
#pragma unroll
                for (int su = 0; su < 4; su++) {
                    vx[slot][su][0] = *(const float4*)(p0 + (size_t)(4 * (hidx + 2) + su) * 16);
                    vx[slot][su][1] = *(const float4*)(p1 + (size_t)(4 * (hidx + 2) + su) * 16);
                }
            }

            // 16 HMMA: 4 substeps x 2 mblocks x {g0, g1}
            const uint32_t hbase = cbase + half * 4 * STEP_BYTES;
#pragma unroll
            for (int su = 0; su < 4; su++) {
#pragma unroll
                for (int mb = 0; mb < 2; mb++) {
                    uint32_t A[4];
                    LDS128(A, hbase + su * STEP_BYTES + (eh * 2 + mb) * 512);
                    MMA(D[mb][0], A, Bs[su][0][0], Bs[su][0][1]);
                    MMA(D[mb][1], A, Bs[su][1][0], Bs[su][1][1]);
                }
            }
        }
    }

    // All warps must be done reading the smem ring before slog overwrites it.
    __syncthreads();

    // ---- epilogue: stage logits in smem ----
    float* slog = (float*)smem;   // pitch 65 floats per token
#pragma unroll
    for (int mb = 0; mb < 2; mb++) {
        int e0 = (eh * 2 + mb) * 16 + (l >> 2);
        int e1 = e0 + 8;
#pragma unroll
        for (int g = 0; g < 2; g++) {
            int tk = tg * 16 + g * 8 + 2 * q;
            slog[(size_t)tk * 65 + e0]       = D[mb][g][0] * INV_WS;
            slog[(size_t)(tk + 1) * 65 + e0] = D[mb][g][1] * INV_WS;
            slog[(size_t)tk * 65 + e1]       = D[mb][g][2] * INV_WS;
            slog[(size_t)(tk + 1) * 65 + e1] = D[mb][g][3] * INV_WS;
        }
    }
    __syncthreads();

    if (tid < MTILE) {
        const float* row = slog + (size_t)tid * 65;
        float m1 = -3.4e38f, m2 = -3.4e38f, m3 = -3.4e38f;
        int i1 = 0, i2 = 0;
        float lg[NEXP];
#pragma unroll
        for (int e = 0; e < NEXP; e++) {
            float vv = row[e] + bias[e];
            lg[e] = vv;
            if (vv > m1)      { m3 = m2; m2 = m1; i2 = i1; m1 = vv; i1 = e; }
            else if (vv > m2) { m3 = m2; m2 = vv; i2 = e; }
            else if (vv > m3) { m3 = vv; }
        }
        float s = 0.0f;
#pragma unroll
        for (int e = 0; e < NEXP; e++) s += __expf(lg[e] - m1);

        const float v1 = 1.0f / s;
        const float v2 = __expf(m2 - m1) * v1;
        const int token = blockIdx.x * MTILE + tid;
        ((float2*)out)[token] = make_float2(v1, v2);
        ((float2*)(out + 2 * NTOK))[token] = make_float2((float)i1, (float)i2);

        if ((m1 - m2) < GAP_THR || (m2 - m3) < GAP_THR) {
            int slot = atomicAdd(&g_flag_count, 1);
            if (slot < NTOK) g_flag_tokens[slot] = token;
        }
    }
}

// ---------------------------------------------------------------------------
// Fixup: exact fp32 recompute of flagged tokens (warp-per-8-experts, shuffle
// reduction; W stays L2-hot).
// ---------------------------------------------------------------------------
__global__ __launch_bounds__(256, 1)
void fixup_kernel(const float* __restrict__ x,
                  const float* __restrict__ W,
                  const float* __restrict__ bias,
                  float* __restrict__ out) {
    __shared__ float xs[HIDDEN];
    __shared__ float lg[NEXP];
    const int tid = threadIdx.x;
    const int w = tid >> 5, l = tid & 31;
    const int cnt = min(g_flag_count, NTOK);

    for (int i = blockIdx.x; i < cnt; i += gridDim.x) {
        const int tok = g_flag_tokens[i];
        __syncthreads();
        for (int j = tid; j < HIDDEN / 4; j += 256)
            ((float4*)xs)[j] = ((const float4*)(x + (size_t)tok * HIDDEN))[j];
        __syncthreads();

#pragma unroll
        for (int e8 = 0; e8 < 8; e8++) {
            const int e = w * 8 + e8;
            const float* wr = W + (size_t)e * HIDDEN;
            float s = 0.0f;
#pragma unroll 8
            for (int k = l * 4; k < HIDDEN; k += 128) {
                float4 a = *(const float4*)(xs + k);
                float4 bb = *(const float4*)(wr + k);
                s += a.x * bb.x + a.y * bb.y + a.z * bb.z + a.w * bb.w;
            }
#pragma unroll
            for (int o = 16; o; o >>= 1) s += __shfl_xor_sync(0xFFFFFFFFu, s, o);
            if (l == 0) lg[e] = s + bias[e];
        }
        __syncthreads();

        if (tid == 0) {
            float m1 = -3.4e38f, m2 = -3.4e38f;
            int i1 = 0, i2 = 0;
            for (int ee = 0; ee < NEXP; ee++) {
                float vv = lg[ee];
                if (vv > m1)      { m2 = m1; i2 = i1; m1 = vv; i1 = ee; }
                else if (vv > m2) { m2 = vv; i2 = ee; }
            }
            float ssum = 0.0f;
            for (int ee = 0; ee < NEXP; ee++) ssum += __expf(lg[ee] - m1);
            const float v1 = 1.0f / ssum;
            const float v2 = __expf(m2 - m1) * v1;
            ((float2*)out)[tok] = make_float2(v1, v2);
            ((float2*)(out + 2 * NTOK))[tok] = make_float2((float)i1, (float)i2);
        }
        __syncthreads();
    }
}

// ---------------------------------------------------------------------------
extern "C" void kernel_launch(void* const* d_in, const int* in_sizes, int n_in,
                              void* d_out, int out_size) {
    const float* x = (const float*)d_in[0];
    const float* W = (const float*)d_in[1];
    const float* b = (const float*)d_in[2];
    float* out = (float*)d_out;

    cudaFuncSetAttribute(gating_kernel, cudaFuncAttributeMaxDynamicSharedMemorySize,
                         SMEM_TOTAL);

    prep_w_kernel<<<(NSTEP * FRAG_PER_STEP + 255) / 256, 256>>>(W);
    gating_kernel<<<NCTA, THREADS, SMEM_TOTAL>>>(x, b, out);
    fixup_kernel<<<128, 256>>>(x, W, b, out);
}

// round 14
// speedup vs baseline: 1.0444x; 1.0444x over previous
#include <cuda_runtime.h>
#include <cuda_fp16.h>
#include <cstdint>

// ---------------------------------------------------------------------------
// GatingNetwork: logits = x @ W^T + b ; softmax ; top-2 (values, indices)
// Single-product fp16 HMMA (m16n8k16.f16, fp32 accum). W pre-scaled x256
// (exact), logit = D/256 + b. Logit error sigma ~1.4e-4; tokens with any
// top-3 gap < 8e-4 recomputed exactly in fp32 by the fixup kernel.
// BARRIER-FREE main loop: A fragments are loaded directly from the L2-resident
// g_Wfrag image with coalesced LDG.128 (no smem ring, no cp.async, no
// __syncthreads) so warps never collectively drain/refill their pipelines.
// ---------------------------------------------------------------------------

#define HIDDEN   4096
#define NEXP     64
#define NTOK     16384
#define MTILE    128
#define NCTA     (NTOK / MTILE)        // 128
#define THREADS  256
#define NSTEP    (HIDDEN / 16)         // 256 k16-steps
#define NHALF    (NSTEP / 4)           // 64 k64-halves
#define GAP_THR  8e-4f
#define WSCALE   256.0f
#define INV_WS   (1.0f / 256.0f)

// per k16 step: 4 mblocks x 32 lanes x uint4 (fp16, single image)
#define FRAG_PER_STEP   (4 * 32)               // 128 uint4 = 2 KB
#define SMEM_TOTAL      (MTILE * 65 * 4)       // 33280 (epilogue staging only)

__device__ uint4 g_Wfrag[NSTEP * FRAG_PER_STEP];   // 512 KB, L2-resident
__device__ int   g_flag_count;
__device__ int   g_flag_tokens[NTOK];

// pack f16x2: hi = f16(f_odd), lo = f16(f_even)
static __device__ __forceinline__ uint32_t pack2h(float f_even, float f_odd) {
    uint32_t r;
    asm("cvt.rn.f16x2.f32 %0, %1, %2;" : "=r"(r) : "f"(f_odd), "f"(f_even));
    return r;
}

#define MMA(D, A, B0, B1)                                                     \
    asm volatile(                                                             \
        "mma.sync.aligned.m16n8k16.row.col.f32.f16.f16.f32 "                  \
        "{%0,%1,%2,%3},{%4,%5,%6,%7},{%8,%9},{%0,%1,%2,%3};"                  \
        : "+f"((D)[0]), "+f"((D)[1]), "+f"((D)[2]), "+f"((D)[3])              \
        : "r"((A).x), "r"((A).y), "r"((A).z), "r"((A).w), "r"(B0), "r"(B1))

// ---------------------------------------------------------------------------
// Prep: W * 256 -> fp16 fragments with the permuted-K layout.
// idx = (t*4 + mb)*32 + lane.
// ---------------------------------------------------------------------------
__global__ void prep_w_kernel(const float* __restrict__ W) {
    int idx = blockIdx.x * blockDim.x + threadIdx.x;
    if (idx == 0) g_flag_count = 0;
    if (idx >= NSTEP * FRAG_PER_STEP) return;
    int l = idx & 31;
    int r = idx >> 5;
    int mb = r & 3;
    int t = r >> 2;

    int q = l & 3;
    int row0 = mb * 16 + (l >> 2);
    int row1 = row0 + 8;
    int c = t * 16 + 4 * q;

    const float* w0 = W + (size_t)row0 * HIDDEN + c;
    const float* w1 = W + (size_t)row1 * HIDDEN + c;

    uint4 v;
    v.x = pack2h(w0[0] * WSCALE, w0[1] * WSCALE);
    v.y = pack2h(w1[0] * WSCALE, w1[1] * WSCALE);
    v.z = pack2h(w0[2] * WSCALE, w0[3] * WSCALE);
    v.w = pack2h(w1[2] * WSCALE, w1[3] * WSCALE);
    g_Wfrag[idx] = v;
}

// ---------------------------------------------------------------------------
// Main kernel: 8 warps; warp w owns tokens [blk*128 + w*16, +16) x 64 experts.
// Loop over 64 k64 halves, unrolled 4x; A fragments LDG'd from L2.
// ---------------------------------------------------------------------------
__global__ __launch_bounds__(THREADS, 1)
void gating_kernel(const float* __restrict__ x,
                   const float* __restrict__ bias,
                   float* __restrict__ out) {
    extern __shared__ char smem[];
    const int tid = threadIdx.x;
    const int w   = tid >> 5;
    const int l   = tid & 31;
    const int q   = l & 3;

    // lane's x rows: token tbase + l/4 (g1: +8); within k16-step: float4 at 4q
    const int tbase = blockIdx.x * MTILE + w * 16;
    const float* p0 = x + (size_t)(tbase + (l >> 2)) * HIDDEN + 4 * q;
    const float* p1 = p0 + (size_t)8 * HIDDEN;

    // lane's A-fragment stream: element l of each (step, mb) record
    const uint4* wf = g_Wfrag + l;

    // x pipeline: [slot][substep][g] float4, slot = k64-half parity
    float4 vx[2][4][2];
#pragma unroll
    for (int d = 0; d < 2; d++)
#pragma unroll
        for (int su = 0; su < 4; su++) {
            vx[d][su][0] = *(const float4*)(p0 + (size_t)(4 * d + su) * 16);
            vx[d][su][1] = *(const float4*)(p1 + (size_t)(4 * d + su) * 16);
        }

    float D[4][2][4];
#pragma unroll
    for (int mb = 0; mb < 4; mb++)
#pragma unroll
        for (int g = 0; g < 2; g++)
#pragma unroll
            for (int i = 0; i < 4; i++) D[mb][g][i] = 0.0f;

#pragma unroll 1
    for (int hh = 0; hh < NHALF; hh += 4) {
        // ---- four k64 halves unrolled; no barriers anywhere ----
#pragma unroll
        for (int half = 0; half < 4; half++) {
            const int hidx = hh + half;
            const int slot = hidx & 1;

            // B fragments: Bs[substep][g][2] straight from float4
            uint32_t Bs[4][2][2];
#pragma unroll
            for (int su = 0; su < 4; su++)
#pragma unroll
                for (int g = 0; g < 2; g++) {
                    float4 f = vx[slot][su][g];
                    Bs[su][g][0] = pack2h(f.x, f.y);   // slots 2q,2q+1
                    Bs[su][g][1] = pack2h(f.z, f.w);   // slots 2q+8,2q+9
                }

            // prefetch x for half hidx+2 into this slot
            if (hidx + 2 < NHALF) {
#pragma unroll
                for (int su = 0; su < 4; su++) {
                    vx[slot][su][0] = *(const float4*)(p0 + (size_t)(4 * (hidx + 2) + su) * 16);
                    vx[slot][su][1] = *(const float4*)(p1 + (size_t)(4 * (hidx + 2) + su) * 16);
                }
            }

            // 32 HMMA: 4 substeps x 4 mblocks x {g0, g1}; A from L2 via LDG
#pragma unroll
            for (int su = 0; su < 4; su++) {
                const uint4* astep = wf + (size_t)((hidx * 4 + su) * 4) * 32;
                uint4 A0 = __ldg(astep);
                uint4 A1 = __ldg(astep + 32);
                uint4 A2 = __ldg(astep + 64);
                uint4 A3 = __ldg(astep + 96);
                MMA(D[0][0], A0, Bs[su][0][0], Bs[su][0][1]);
                MMA(D[0][1], A0, Bs[su][1][0], Bs[su][1][1]);
                MMA(D[1][0], A1, Bs[su][0][0], Bs[su][0][1]);
                MMA(D[1][1], A1, Bs[su][1][0], Bs[su][1][1]);
                MMA(D[2][0], A2, Bs[su][0][0], Bs[su][0][1]);
                MMA(D[2][1], A2, Bs[su][1][0], Bs[su][1][1]);
                MMA(D[3][0], A3, Bs[su][0][0], Bs[su][0][1]);
                MMA(D[3][1], A3, Bs[su][1][0], Bs[su][1][1]);
            }
        }
    }

    // ---- epilogue: stage logits in smem ----
    float* slog = (float*)smem;   // pitch 65 floats per token
#pragma unroll
    for (int mb = 0; mb < 4; mb++) {
        int e0 = mb * 16 + (l >> 2);
        int e1 = e0 + 8;
#pragma unroll
        for (int g = 0; g < 2; g++) {
            int tk = w * 16 + g * 8 + 2 * q;
            slog[(size_t)tk * 65 + e0]       = D[mb][g][0] * INV_WS;
            slog[(size_t)(tk + 1) * 65 + e0] = D[mb][g][1] * INV_WS;
            slog[(size_t)tk * 65 + e1]       = D[mb][g][2] * INV_WS;
            slog[(size_t)(tk + 1) * 65 + e1] = D[mb][g][3] * INV_WS;
        }
    }
    __syncthreads();

    if (tid < MTILE) {
        const float* row = slog + (size_t)tid * 65;
        float m1 = -3.4e38f, m2 = -3.4e38f, m3 = -3.4e38f;
        int i1 = 0, i2 = 0;
        float lg[NEXP];
#pragma unroll
        for (int e = 0; e < NEXP; e++) {
            float vv = row[e] + bias[e];
            lg[e] = vv;
            if (vv > m1)      { m3 = m2; m2 = m1; i2 = i1; m1 = vv; i1 = e; }
            else if (vv > m2) { m3 = m2; m2 = vv; i2 = e; }
            else if (vv > m3) { m3 = vv; }
        }
        float s = 0.0f;
#pragma unroll
        for (int e = 0; e < NEXP; e++) s += __expf(lg[e] - m1);

        const float v1 = 1.0f / s;
        const float v2 = __expf(m2 - m1) * v1;
        const int token = blockIdx.x * MTILE + tid;
        ((float2*)out)[token] = make_float2(v1, v2);
        ((float2*)(out + 2 * NTOK))[token] = make_float2((float)i1, (float)i2);

        if ((m1 - m2) < GAP_THR || (m2 - m3) < GAP_THR) {
            int slot = atomicAdd(&g_flag_count, 1);
            if (slot < NTOK) g_flag_tokens[slot] = token;
        }
    }
}

// ---------------------------------------------------------------------------
// Fixup: exact fp32 recompute of flagged tokens (warp-per-8-experts, shuffle
// reduction; W stays L2-hot).
// ---------------------------------------------------------------------------
__global__ __launch_bounds__(256, 1)
void fixup_kernel(const float* __restrict__ x,
                  const float* __restrict__ W,
                  const float* __restrict__ bias,
                  float* __restrict__ out) {
    __shared__ float xs[HIDDEN];
    __shared__ float lg[NEXP];
    const int tid = threadIdx.x;
    const int w = tid >> 5, l = tid & 31;
    const int cnt = min(g_flag_count, NTOK);

    for (int i = blockIdx.x; i < cnt; i += gridDim.x) {
        const int tok = g_flag_tokens[i];
        __syncthreads();
        for (int j = tid; j < HIDDEN / 4; j += 256)
            ((float4*)xs)[j] = ((const float4*)(x + (size_t)tok * HIDDEN))[j];
        __syncthreads();

#pragma unroll
        for (int e8 = 0; e8 < 8; e8++) {
            const int e = w * 8 + e8;
            const float* wr = W + (size_t)e * HIDDEN;
            float s = 0.0f;
#pragma unroll 8
            for (int k = l * 4; k < HIDDEN; k += 128) {
                float4 a = *(const float4*)(xs + k);
                float4 bb = *(const float4*)(wr + k);
                s += a.x * bb.x + a.y * bb.y + a.z * bb.z + a.w * bb.w;
            }
#pragma unroll
            for (int o = 16; o; o >>= 1) s += __shfl_xor_sync(0xFFFFFFFFu, s, o);
            if (l == 0) lg[e] = s + bias[e];
        }
        __syncthreads();

        if (tid == 0) {
            float m1 = -3.4e38f, m2 = -3.4e38f;
            int i1 = 0, i2 = 0;
            for (int ee = 0; ee < NEXP; ee++) {
                float vv = lg[ee];
                if (vv > m1)      { m2 = m1; i2 = i1; m1 = vv; i1 = ee; }
                else if (vv > m2) { m2 = vv; i2 = ee; }
            }
            float ssum = 0.0f;
            for (int ee = 0; ee < NEXP; ee++) ssum += __expf(lg[ee] - m1);
            const float v1 = 1.0f / ssum;
            const float v2 = __expf(m2 - m1) * v1;
            ((float2*)out)[tok] = make_float2(v1, v2);
            ((float2*)(out + 2 * NTOK))[tok] = make_float2((float)i1, (float)i2);
        }
        __syncthreads();
    }
}

// ---------------------------------------------------------------------------
extern "C" void kernel_launch(void* const* d_in, const int* in_sizes, int n_in,
                              void* d_out, int out_size) {
    const float* x = (const float*)d_in[0];
    const float* W = (const float*)d_in[1];
    const float* b = (const float*)d_in[2];
    float* out = (float*)d_out;

    cudaFuncSetAttribute(gating_kernel, cudaFuncAttributeMaxDynamicSharedMemorySize,
                         SMEM_TOTAL);

    prep_w_kernel<<<(NSTEP * FRAG_PER_STEP + 255) / 256, 256>>>(W);
    gating_kernel<<<NCTA, THREADS, SMEM_TOTAL>>>(x, b, out);
    fixup_kernel<<<128, 256>>>(x, W, b, out);
}